// round 15
// baseline (speedup 1.0000x reference)
#include <cuda_runtime.h>
#include <cuda_bf16.h>
#include <cstdint>
#include <math.h>

// Problem constants
#define B   32
#define S   512
#define H   1024
#define T   37
#define LP  39
#define BS  (B*S)          // 16384
#define ZK3 2176           // 1024 (h) + 1024 (h*aware) + 64 (attn) + 64 (pad) ; 17*128
#define KSPLIT 8

// FP8 section scales: product scale is uniformly 256, undone in k2 epilogue.
//   Z:  h x1,  h*aware x32, attn x16
//   W:  h-rows x256, ha-rows x8, attn-rows x16
#define ZSC_HA 32.0f
#define ZSC_AT 16.0f
#define WSC_H  256.0f
#define WSC_HA 8.0f
#define WSC_AT 16.0f
#define OUT_SCL (1.0f/256.0f)

// Scratch (device-global)
__device__ __align__(256) uint8_t g_Z8[BS * ZK3];        // fp8 Z, 35.6 MB
__device__ __align__(256) uint8_t g_W8[H * ZK3];         // fp8 W', 2.2 MB
__device__ __align__(256) __nv_bfloat16 g_Yb[BS * H];    // gelu out, bf16, 32 MiB
__device__ __align__(256) __nv_bfloat16 g_W3[64 * H];    // W_crf^T padded, bf16
__device__ __align__(256) float g_BW2p[KSPLIT * T * H];  // bw2 partials, 1.2 MiB

// ===========================================================================
// helpers
// ===========================================================================
__device__ __forceinline__ uint32_t smem_u32(const void* p) {
    uint32_t a;
    asm("{ .reg .u64 t; cvta.to.shared.u64 t, %1; cvt.u32.u64 %0, t; }"
        : "=r"(a) : "l"(p));
    return a;
}
__device__ __forceinline__ void cp16(uint32_t dst, const void* src) {
    asm volatile("cp.async.cg.shared.global [%0], [%1], 16;\n" :: "r"(dst), "l"(src));
}
#define CP_COMMIT() asm volatile("cp.async.commit_group;\n" ::: "memory")
#define CP_WAIT(n)  asm volatile("cp.async.wait_group %0;\n" :: "n"(n) : "memory")

__device__ __forceinline__ float gelu(float v) {
    return 0.5f * v * (1.f + erff(v * 0.70710678118654752f));
}
__device__ __forceinline__ void ldsm4(uint32_t* r, uint32_t addr) {
    asm volatile("ldmatrix.sync.aligned.m8n8.x4.shared.b16 {%0,%1,%2,%3}, [%4];"
        : "=r"(r[0]), "=r"(r[1]), "=r"(r[2]), "=r"(r[3]) : "r"(addr));
}
__device__ __forceinline__ void mma_bf16(
    float* d, const uint32_t* a, uint32_t b0, uint32_t b1)
{
    asm volatile(
        "mma.sync.aligned.m16n8k16.row.col.f32.bf16.bf16.f32 "
        "{%0,%1,%2,%3}, {%4,%5,%6,%7}, {%8,%9}, {%0,%1,%2,%3};"
        : "+f"(d[0]), "+f"(d[1]), "+f"(d[2]), "+f"(d[3])
        : "r"(a[0]), "r"(a[1]), "r"(a[2]), "r"(a[3]), "r"(b0), "r"(b1));
}
__device__ __forceinline__ void mma_fp8(
    float* d, const uint32_t* a, uint32_t b0, uint32_t b1)
{
    asm volatile(
        "mma.sync.aligned.m16n8k32.row.col.f32.e4m3.e4m3.f32 "
        "{%0,%1,%2,%3}, {%4,%5,%6,%7}, {%8,%9}, {%0,%1,%2,%3};"
        : "+f"(d[0]), "+f"(d[1]), "+f"(d[2]), "+f"(d[3])
        : "r"(a[0]), "r"(a[1]), "r"(a[2]), "r"(a[3]), "r"(b0), "r"(b1));
}
__device__ __forceinline__ float rmax32(float x) {
    uint32_t k = __float_as_uint(x);
    k = (k & 0x80000000u) ? ~k : (k | 0x80000000u);
    k = __reduce_max_sync(0xFFFFFFFFu, k);
    return __uint_as_float((k & 0x80000000u) ? (k & 0x7FFFFFFFu) : ~k);
}
__device__ __forceinline__ uint2 pack4bf(float4 v) {
    __nv_bfloat162 p0; p0.x = __float2bfloat16(v.x); p0.y = __float2bfloat16(v.y);
    __nv_bfloat162 p1; p1.x = __float2bfloat16(v.z); p1.y = __float2bfloat16(v.w);
    uint2 r; r.x = *(uint32_t*)&p0; r.y = *(uint32_t*)&p1; return r;
}
// packed: low byte = v0, high byte = v1
__device__ __forceinline__ uint16_t e4m3x2(float v0, float v1) {
    uint16_t r;
    asm("cvt.rn.satfinite.e4m3x2.f32 %0, %1, %2;" : "=h"(r) : "f"(v1), "f"(v0));
    return r;
}
__device__ __forceinline__ uint32_t e4m3x4(float a, float b, float c, float d) {
    return (uint32_t)e4m3x2(a, b) | ((uint32_t)e4m3x2(c, d) << 16);
}

// ---------------------------------------------------------------------------
// k_bw2: partial[by][t][n] = sum_{k in chunk} bio[t][k] * W_cat[1024+k][n]
// ---------------------------------------------------------------------------
__global__ __launch_bounds__(256) void k_bw2(
    const float* __restrict__ bio, const float* __restrict__ W)
{
    __shared__ float bioS[T * 128 + 32];
    int tid = threadIdx.x;
    int k0 = blockIdx.y * 128;
    for (int i = tid; i < T * 32; i += 256) {
        int t = i >> 5, c = i & 31;
        ((float4*)&bioS[t*128])[c] = ((const float4*)(bio + (size_t)t * H + k0))[c];
    }
    __syncthreads();

    int n = blockIdx.x * 32 + (tid & 31);
    int th = tid >> 5;
    float acc[5] = {0.f, 0.f, 0.f, 0.f, 0.f};
    #pragma unroll 4
    for (int k = 0; k < 128; k++) {
        float w = W[(size_t)(H + k0 + k) * H + n];
        #pragma unroll
        for (int j = 0; j < 5; j++) {
            int t = th + 8*j;
            float bv = (t < T) ? bioS[t*128 + k] : 0.f;
            acc[j] += bv * w;
        }
    }
    float* pp = g_BW2p + (size_t)blockIdx.y * T * H;
    #pragma unroll
    for (int j = 0; j < 5; j++) {
        int t = th + 8*j;
        if (t < T) pp[t*H + n] = acc[j];
    }
}

// ---------------------------------------------------------------------------
// kprep: merged prep.
//  blocks [0,2048):      g_W8[n][k] = fp8(W_cat[src(k)][n] * sec_scale), k<2048
//  blocks [2048,2112):   g_W3[t][k] = bf16(W_crf[k][t]) (t>=T zero)
//  blocks [2112,2624):   g_W8[n][2048+c] = fp8(bw2_sum*16) for c<T else 0, c<128
// ---------------------------------------------------------------------------
__global__ __launch_bounds__(256) void kprep(
    const float* __restrict__ W, const float* __restrict__ Wc)
{
    __shared__ float tile[32][33];
    int bid = blockIdx.x;
    int tid = threadIdx.x;
    int tx = tid & 31, ty = tid >> 5;

    if (bid < 2048) {
        int k0 = (bid & 63) * 32;
        int n0 = (bid >> 6) * 32;
        #pragma unroll
        for (int j = 0; j < 32; j += 8) {
            int k = k0 + ty + j;
            int src = (k < H) ? k : (k + H);
            tile[ty + j][tx] = W[(size_t)src * H + n0 + tx];
        }
        __syncthreads();
        float scl = (k0 + tx < H) ? WSC_H : WSC_HA;
        #pragma unroll
        for (int j = 0; j < 32; j += 8) {
            int n = n0 + ty + j;
            uint16_t p = e4m3x2(tile[tx][ty + j] * scl, 0.f);
            g_W8[(size_t)n * ZK3 + k0 + tx] = (uint8_t)p;
        }
    } else if (bid < 2112) {
        int b2 = bid - 2048;
        int k0 = (b2 & 31) * 32;
        int t0 = (b2 >> 5) * 32;
        #pragma unroll
        for (int j = 0; j < 32; j += 8) {
            int k = k0 + ty + j, t = t0 + tx;
            tile[ty + j][tx] = (t < T) ? Wc[(size_t)k * T + t] : 0.f;
        }
        __syncthreads();
        #pragma unroll
        for (int j = 0; j < 32; j += 8) {
            int t = t0 + ty + j;
            g_W3[(size_t)t * H + k0 + tx] = __float2bfloat16(tile[tx][ty + j]);
        }
    } else {
        int idx = (bid - 2112) * 256 + tid;   // 0 .. H*128-1
        int n = idx >> 7, c = idx & 127;
        float s = 0.f;
        if (c < T) {
            #pragma unroll
            for (int q = 0; q < KSPLIT; q++)
                s += g_BW2p[(size_t)q * T * H + c*H + n];
        }
        uint16_t p = e4m3x2(s * WSC_AT, 0.f);
        g_W8[(size_t)n * ZK3 + 2048 + c] = (uint8_t)p;
    }
}

// ---------------------------------------------------------------------------
// k1: 2 rows per warp, bf16 bio tile in smem, HFMA2 arithmetic,
// fp8 Z output with section scaling.
// ---------------------------------------------------------------------------
__global__ __launch_bounds__(256, 2) void k1_bio_attn(
    const float* __restrict__ h, const float* __restrict__ bio)
{
    extern __shared__ __align__(16) __nv_bfloat16 bioB[];   // [T][H] bf16
    int tid = threadIdx.x;
    for (int i = tid; i < T*H/2; i += 256) {
        float2 v = ((const float2*)bio)[i];
        __nv_bfloat162 p; p.x = __float2bfloat16(v.x); p.y = __float2bfloat16(v.y);
        ((__nv_bfloat162*)bioB)[i] = p;
    }
    __syncthreads();

    int wid = tid >> 5, l = tid & 31;
    int row0 = (blockIdx.x * 8 + wid) * 2;
    int row1 = row0 + 1;
    const uint2* bB = (const uint2*)bioB;

    uint8_t* zr0 = g_Z8 + (size_t)row0 * ZK3;
    uint8_t* zr1 = g_Z8 + (size_t)row1 * ZK3;

    uint2 h0p[8], h1p[8];
    {
        const float4* p0 = (const float4*)(h + (size_t)row0 * H);
        const float4* p1 = (const float4*)(h + (size_t)row1 * H);
        #pragma unroll
        for (int j = 0; j < 8; j++) {
            float4 v0 = p0[j*32 + l];
            float4 v1 = p1[j*32 + l];
            h0p[j] = pack4bf(v0);
            h1p[j] = pack4bf(v1);
            *(uint32_t*)(zr0 + j*128 + 4*l) = e4m3x4(v0.x, v0.y, v0.z, v0.w);
            *(uint32_t*)(zr1 + j*128 + 4*l) = e4m3x4(v1.x, v1.y, v1.z, v1.w);
        }
        // zero pad bytes [2112, 2176)
        if (l < 16) {
            *(uint32_t*)(zr0 + 2112 + 4*l) = 0u;
            *(uint32_t*)(zr1 + 2112 + 4*l) = 0u;
        }
    }

    float v0a = -1e30f, v0b = -1e30f, v1a = -1e30f, v1b = -1e30f;
    const __nv_bfloat162 z2 = __float2bfloat162_rn(0.f);
    for (int t = 0; t < T; t++) {
        const uint2* bt = bB + t*256;
        __nv_bfloat162 a0a = z2, a0b = z2, a1a = z2, a1b = z2;
        #pragma unroll
        for (int j = 0; j < 8; j++) {
            uint2 pk = bt[j*32 + l];
            __nv_bfloat162 b01 = *(__nv_bfloat162*)&pk.x;
            __nv_bfloat162 b23 = *(__nv_bfloat162*)&pk.y;
            a0a = __hfma2(b01, *(__nv_bfloat162*)&h0p[j].x, a0a);
            a0b = __hfma2(b23, *(__nv_bfloat162*)&h0p[j].y, a0b);
            a1a = __hfma2(b01, *(__nv_bfloat162*)&h1p[j].x, a1a);
            a1b = __hfma2(b23, *(__nv_bfloat162*)&h1p[j].y, a1b);
        }
        float2 f0 = __bfloat1622float2(a0a), f0q = __bfloat1622float2(a0b);
        float2 f1 = __bfloat1622float2(a1a), f1q = __bfloat1622float2(a1b);
        float s0 = (f0.x + f0.y) + (f0q.x + f0q.y);
        float s1 = (f1.x + f1.y) + (f1q.x + f1q.y);
        #pragma unroll
        for (int o = 16; o; o >>= 1) {
            s0 += __shfl_xor_sync(~0u, s0, o);
            s1 += __shfl_xor_sync(~0u, s1, o);
        }
        s0 *= 0.03125f; s1 *= 0.03125f;
        if (t < 32) { if (l == t)    { v0a = s0; v1a = s1; } }
        else        { if (l == t-32) { v0b = s0; v1b = s1; } }
    }

    float e0a, e0b, e1a, e1b;
    {
        float m0 = rmax32(fmaxf(v0a, (l < T-32) ? v0b : -1e30f));
        e0a = __expf(v0a - m0);
        e0b = (l < T-32) ? __expf(v0b - m0) : 0.f;
        float ss = e0a + e0b;
        #pragma unroll
        for (int o = 16; o; o >>= 1) ss += __shfl_xor_sync(~0u, ss, o);
        float inv = 1.f / ss; e0a *= inv; e0b *= inv;

        float m1 = rmax32(fmaxf(v1a, (l < T-32) ? v1b : -1e30f));
        e1a = __expf(v1a - m1);
        e1b = (l < T-32) ? __expf(v1b - m1) : 0.f;
        float s1s = e1a + e1b;
        #pragma unroll
        for (int o = 16; o; o >>= 1) s1s += __shfl_xor_sync(~0u, s1s, o);
        float inv1 = 1.f / s1s; e1a *= inv1; e1b *= inv1;
    }

    // attn columns [2048, 2112), scaled x16, fp8
    {
        int i0 = 2*l, i1 = 2*l + 1;
        float r0lo0 = __shfl_sync(~0u, e0a, i0 & 31);
        float r0hi0 = __shfl_sync(~0u, e0b, (i0 >= 32) ? (i0 - 32) : 0);
        float r0lo1 = __shfl_sync(~0u, e0a, i1 & 31);
        float r0hi1 = __shfl_sync(~0u, e0b, (i1 >= 32) ? (i1 - 32) : 0);
        float r1lo0 = __shfl_sync(~0u, e1a, i0 & 31);
        float r1hi0 = __shfl_sync(~0u, e1b, (i0 >= 32) ? (i0 - 32) : 0);
        float r1lo1 = __shfl_sync(~0u, e1a, i1 & 31);
        float r1hi1 = __shfl_sync(~0u, e1b, (i1 >= 32) ? (i1 - 32) : 0);
        float a00 = (i0 < 32) ? r0lo0 : r0hi0; if (i0 >= T) a00 = 0.f;
        float a01 = (i1 < 32) ? r0lo1 : r0hi1; if (i1 >= T) a01 = 0.f;
        float a10 = (i0 < 32) ? r1lo0 : r1hi0; if (i0 >= T) a10 = 0.f;
        float a11 = (i1 < 32) ? r1lo1 : r1hi1; if (i1 >= T) a11 = 0.f;
        *(uint16_t*)(zr0 + 2048 + 2*l) = e4m3x2(a00 * ZSC_AT, a01 * ZSC_AT);
        *(uint16_t*)(zr1 + 2048 + 2*l) = e4m3x2(a10 * ZSC_AT, a11 * ZSC_AT);
    }

    // aware accumulation in bf16x2
    __nv_bfloat162 aw0[16], aw1[16];
    #pragma unroll
    for (int j = 0; j < 16; j++) { aw0[j] = z2; aw1[j] = z2; }
    for (int t = 0; t < T; t++) {
        float a0f = (t < 32) ? __shfl_sync(~0u, e0a, t) : __shfl_sync(~0u, e0b, t - 32);
        float a1f = (t < 32) ? __shfl_sync(~0u, e1a, t) : __shfl_sync(~0u, e1b, t - 32);
        __nv_bfloat162 a0v = __float2bfloat162_rn(a0f);
        __nv_bfloat162 a1v = __float2bfloat162_rn(a1f);
        const uint2* bt = bB + t*256;
        #pragma unroll
        for (int j = 0; j < 8; j++) {
            uint2 pk = bt[j*32 + l];
            __nv_bfloat162 b01 = *(__nv_bfloat162*)&pk.x;
            __nv_bfloat162 b23 = *(__nv_bfloat162*)&pk.y;
            aw0[2*j]   = __hfma2(b01, a0v, aw0[2*j]);
            aw0[2*j+1] = __hfma2(b23, a0v, aw0[2*j+1]);
            aw1[2*j]   = __hfma2(b01, a1v, aw1[2*j]);
            aw1[2*j+1] = __hfma2(b23, a1v, aw1[2*j+1]);
        }
    }

    // product h * aware, scaled x32, fp8 store
    #pragma unroll
    for (int j = 0; j < 8; j++) {
        float2 ax = __bfloat1622float2(aw0[2*j]);
        float2 ay = __bfloat1622float2(aw0[2*j+1]);
        float2 hx = __bfloat1622float2(*(__nv_bfloat162*)&h0p[j].x);
        float2 hy = __bfloat1622float2(*(__nv_bfloat162*)&h0p[j].y);
        *(uint32_t*)(zr0 + 1024 + j*128 + 4*l) =
            e4m3x4(ax.x*hx.x*ZSC_HA, ax.y*hx.y*ZSC_HA, ay.x*hy.x*ZSC_HA, ay.y*hy.y*ZSC_HA);
        ax = __bfloat1622float2(aw1[2*j]);
        ay = __bfloat1622float2(aw1[2*j+1]);
        hx = __bfloat1622float2(*(__nv_bfloat162*)&h1p[j].x);
        hy = __bfloat1622float2(*(__nv_bfloat162*)&h1p[j].y);
        *(uint32_t*)(zr1 + 1024 + j*128 + 4*l) =
            e4m3x4(ax.x*hx.x*ZSC_HA, ax.y*hx.y*ZSC_HA, ay.x*hy.x*ZSC_HA, ay.y*hy.y*ZSC_HA);
    }
}

// ---------------------------------------------------------------------------
// k2: Yb = bf16(gelu(Z8 @ W8^T * (1/256) + bc))  fp8 mma m16n8k32,
// BM=128 BN=128 BK=128(fp8), 3-stage cp.async, 2 CTAs/SM, single sync/iter.
// ---------------------------------------------------------------------------
#define KBM 128
#define KBN 128
#define NKI (ZK3/128)            // 17
#define STG (KBM*128 + KBN*128)  // 32768 bytes
#define SMEM_K2 (3*STG)          // 98304

__device__ __forceinline__ void k2_load_stage(
    uint32_t sb, int tid, int j, const uint8_t* Zb, const uint8_t* Wb)
{
    uint32_t base = sb + (j % 3) * STG;
    int kb = j * 128;                     // bytes along K
    #pragma unroll
    for (int q = 0; q < 8; q++) {
        int idx = tid + 256*q;
        if (q < 4) {
            int m = idx >> 3, c = idx & 7;
            cp16(base + ((m*128 + c*16) ^ ((m & 7) << 4)),
                 Zb + (size_t)m * ZK3 + kb + c*16);
        } else {
            int ci = idx - 1024;
            int n = ci >> 3, c = ci & 7;
            cp16(base + 16384 + ((n*128 + c*16) ^ ((n & 7) << 4)),
                 Wb + (size_t)n * ZK3 + kb + c*16);
        }
    }
}

__global__ __launch_bounds__(256, 2) void k2_mma(const float* __restrict__ bc)
{
    extern __shared__ __align__(16) char smem[];
    uint32_t sb = smem_u32(smem);
    int tid = threadIdx.x, lane = tid & 31, wid = tid >> 5;
    int wm = wid & 3, wn = wid >> 2;          // 4(m) x 2(n), warp tile 32x64
    int row0 = blockIdx.y * KBM, n0 = blockIdx.x * KBN;

    const uint8_t* Zb = g_Z8 + (size_t)row0 * ZK3;
    const uint8_t* Wb = g_W8 + (size_t)n0   * ZK3;

    float acc[2][8][4];
    #pragma unroll
    for (int mt = 0; mt < 2; mt++)
        #pragma unroll
        for (int nt = 0; nt < 8; nt++)
            #pragma unroll
            for (int q = 0; q < 4; q++) acc[mt][nt][q] = 0.f;

    k2_load_stage(sb, tid, 0, Zb, Wb); CP_COMMIT();
    k2_load_stage(sb, tid, 1, Zb, Wb); CP_COMMIT();

    int r15 = lane & 15;
    int hb  = (lane >> 4) << 4;

    for (int i = 0; i < NKI; i++) {
        CP_WAIT(1);
        __syncthreads();

        uint32_t Sb2 = sb + (i % 3) * STG;
        #pragma unroll
        for (int kk = 0; kk < 4; kk++) {       // 4 x k32 per 128B stage
            int kbyte = kk*32 + hb;
            uint32_t a[2][4];
            #pragma unroll
            for (int mt = 0; mt < 2; mt++) {
                int rr = wm*32 + mt*16 + r15;
                ldsm4(a[mt], Sb2 + rr*128 + (kbyte ^ ((rr & 7) << 4)));
            }
            #pragma unroll
            for (int np = 0; np < 4; np++) {
                int nr = wn*64 + np*16 + r15;
                uint32_t b[4];
                ldsm4(b, Sb2 + 16384 + nr*128 + (kbyte ^ ((nr & 7) << 4)));
                #pragma unroll
                for (int mt = 0; mt < 2; mt++) {
                    mma_fp8(acc[mt][2*np],   a[mt], b[0], b[2]);
                    mma_fp8(acc[mt][2*np+1], a[mt], b[1], b[3]);
                }
            }
        }

        int j = i + 2;
        if (j < NKI) k2_load_stage(sb, tid, j, Zb, Wb);
        CP_COMMIT();
    }

    int g = lane >> 2, t4 = lane & 3;
    #pragma unroll
    for (int mt = 0; mt < 2; mt++) {
        #pragma unroll
        for (int nt = 0; nt < 8; nt++) {
            int r0 = row0 + wm*32 + mt*16 + g;
            int c  = n0 + wn*64 + nt*8 + 2*t4;
            float b0v = __ldg(bc + c), b1v = __ldg(bc + c + 1);
            __nv_bfloat162 o0, o1;
            o0.x = __float2bfloat16(gelu(acc[mt][nt][0]*OUT_SCL + b0v));
            o0.y = __float2bfloat16(gelu(acc[mt][nt][1]*OUT_SCL + b1v));
            o1.x = __float2bfloat16(gelu(acc[mt][nt][2]*OUT_SCL + b0v));
            o1.y = __float2bfloat16(gelu(acc[mt][nt][3]*OUT_SCL + b1v));
            *(uint32_t*)(g_Yb + (size_t)r0 * H + c) = *(uint32_t*)&o0;
            *(uint32_t*)(g_Yb + (size_t)(r0 + 8) * H + c) = *(uint32_t*)&o1;
        }
    }
}

// ---------------------------------------------------------------------------
// k3: logits = Yb @ W3^T + b_crf -> ner_scores (+ pads), via bf16 mma.
// ---------------------------------------------------------------------------
#define STG3 (128*128 + 64*128)   // 24576 bytes
#define SMEM_K3 (3*STG3)          // 73728
#define NKI3 (H/64)               // 16

__device__ __forceinline__ void k3_load_stage(
    uint32_t sb, int tid, int j, const char* Yb)
{
    uint32_t base = sb + (j % 3) * STG3;
    int kb = j * 128;
    #pragma unroll
    for (int q = 0; q < 6; q++) {
        int idx = tid + 256*q;
        if (q < 4) {
            int m = idx >> 3, c = idx & 7;
            cp16(base + ((m*128 + c*16) ^ ((m & 7) << 4)),
                 Yb + (size_t)m * (H*2) + kb + c*16);
        } else {
            int ci = idx - 1024;
            int n = ci >> 3, c = ci & 7;
            cp16(base + 16384 + ((n*128 + c*16) ^ ((n & 7) << 4)),
                 (const char*)g_W3 + (size_t)n * (H*2) + kb + c*16);
        }
    }
}

__global__ __launch_bounds__(256, 2) void k3_mma(
    const float* __restrict__ bcrf, float* __restrict__ out)
{
    extern __shared__ __align__(16) char smem[];
    uint32_t sb = smem_u32(smem);
    int tid = threadIdx.x, lane = tid & 31, wid = tid >> 5;
    int wm = wid & 3, wn = wid >> 2;          // 4 x 2
    int row0 = blockIdx.x * 128;

    const char* Yb = (const char*)g_Yb + (size_t)row0 * (H*2);

    float acc[2][4][4];
    #pragma unroll
    for (int mt = 0; mt < 2; mt++)
        #pragma unroll
        for (int nt = 0; nt < 4; nt++)
            #pragma unroll
            for (int q = 0; q < 4; q++) acc[mt][nt][q] = 0.f;

    k3_load_stage(sb, tid, 0, Yb); CP_COMMIT();
    k3_load_stage(sb, tid, 1, Yb); CP_COMMIT();

    int r15 = lane & 15;
    int hb  = (lane >> 4) << 4;

    for (int i = 0; i < NKI3; i++) {
        CP_WAIT(1);
        __syncthreads();

        uint32_t Ab = sb + (i % 3) * STG3;
        uint32_t Bb = Ab + 16384;
        #pragma unroll
        for (int kk = 0; kk < 4; kk++) {
            int kbyte = kk*32 + hb;
            uint32_t a[2][4];
            #pragma unroll
            for (int mt = 0; mt < 2; mt++) {
                int rr = wm*32 + mt*16 + r15;
                ldsm4(a[mt], Ab + rr*128 + (kbyte ^ ((rr & 7) << 4)));
            }
            #pragma unroll
            for (int np = 0; np < 2; np++) {
                int nr = wn*32 + np*16 + r15;
                uint32_t b[4];
                ldsm4(b, Bb + nr*128 + (kbyte ^ ((nr & 7) << 4)));
                #pragma unroll
                for (int mt = 0; mt < 2; mt++) {
                    mma_bf16(acc[mt][2*np],   a[mt], b[0], b[2]);
                    mma_bf16(acc[mt][2*np+1], a[mt], b[1], b[3]);
                }
            }
        }

        int j = i + 2;
        if (j < NKI3) k3_load_stage(sb, tid, j, Yb);
        CP_COMMIT();
    }

    int g = lane >> 2, t4 = lane & 3;
    #pragma unroll
    for (int mt = 0; mt < 2; mt++) {
        int r = row0 + wm*32 + mt*16 + g;
        #pragma unroll
        for (int nt = 0; nt < 4; nt++) {
            int c0 = wn*32 + nt*8 + 2*t4, c1 = c0 + 1;
            if (c0 < T) {
                float bv = __ldg(bcrf + c0);
                out[(size_t)r*LP + c0]     = acc[mt][nt][0] + bv;
                out[(size_t)(r+8)*LP + c0] = acc[mt][nt][2] + bv;
            }
            if (c1 < T) {
                float bv = __ldg(bcrf + c1);
                out[(size_t)r*LP + c1]     = acc[mt][nt][1] + bv;
                out[(size_t)(r+8)*LP + c1] = acc[mt][nt][3] + bv;
            }
        }
        if (wn == 1 && t4 == 0) {
            out[(size_t)r*LP + 37] = -10000.f;  out[(size_t)r*LP + 38] = -10000.f;
            out[(size_t)(r+8)*LP + 37] = -10000.f; out[(size_t)(r+8)*LP + 38] = -10000.f;
        }
    }
}

// ---------------------------------------------------------------------------
// k4: CRF loglik. One warp per batch; lagged-shift LSE scan (exact).
// ---------------------------------------------------------------------------
__global__ __launch_bounds__(32) void k4_crf(
    const float* __restrict__ scores, const int* __restrict__ labels,
    const int* __restrict__ lens, const float* __restrict__ trans,
    float* __restrict__ loss)
{
    extern __shared__ float sc[];
    int b = blockIdx.x;
    int lane = threadIdx.x;
    int len = lens[b];
    const int* lab = labels + b*S;

    {
        uint32_t sbase = smem_u32(sc);
        const float4* src = (const float4*)(scores + (size_t)b * S * LP);
        for (int i = lane; i < S*LP/4; i += 32)
            cp16(sbase + i*16, src + i);
        CP_COMMIT();
        CP_WAIT(0);
        __syncwarp();
    }

    float ET0[LP], ET1[LP], maxT0 = -1e30f, maxT1 = -1e30f;
    {
        const float* tr = trans + lane*LP;
        #pragma unroll
        for (int f = 0; f < LP; f++) maxT0 = fmaxf(maxT0, tr[f]);
        #pragma unroll
        for (int f = 0; f < LP; f++) ET0[f] = __expf(tr[f] - maxT0);
    }
    if (lane < LP-32) {
        const float* tr = trans + (32+lane)*LP;
        #pragma unroll
        for (int f = 0; f < LP; f++) maxT1 = fmaxf(maxT1, tr[f]);
        #pragma unroll
        for (int f = 0; f < LP; f++) ET1[f] = __expf(tr[f] - maxT1);
    }

    float g = 0.f;
    for (int s2 = lane; s2 < len; s2 += 32) g += sc[s2*LP + lab[s2]];
    for (int i = lane; i <= len; i += 32) {
        int frm = (i == 0)   ? T       : lab[i-1];
        int to  = (i == len) ? (T + 1) : lab[i];
        g += trans[to*LP + frm];
    }
    #pragma unroll
    for (int o = 16; o; o >>= 1) g += __shfl_xor_sync(~0u, g, o);

    float a0 = -100.f;
    float a1 = (lane == (T - 32)) ? 0.f : -100.f;
    float s_cur = 0.f, s_next = 0.f;

    for (int t = 0; t < len; t++) {
        float e0 = __expf(a0 - s_cur);
        float e1 = (lane < LP-32) ? __expf(a1 - s_cur) : 0.f;
        float s0a = 0.f, s0b = 0.f, s1a = 0.f, s1b = 0.f;
        #pragma unroll
        for (int f = 0; f < 32; f += 2) {
            float ea = __shfl_sync(~0u, e0, f);
            float eb = __shfl_sync(~0u, e0, f+1);
            s0a += ea*ET0[f];   s0b += eb*ET0[f+1];
            s1a += ea*ET1[f];   s1b += eb*ET1[f+1];
        }
        #pragma unroll
        for (int f = 0; f < LP-32; f++) {
            float ea = __shfl_sync(~0u, e1, f);
            s0a += ea*ET0[32+f];
            s1a += ea*ET1[32+f];
        }
        a0 = sc[t*LP + lane] + s_cur + maxT0 + __logf(s0a + s0b);
        if (lane < LP-32)
            a1 = sc[t*LP + 32 + lane] + s_cur + maxT1 + __logf(s1a + s1b);
        float m = rmax32(fmaxf(a0, (lane < LP-32) ? a1 : -1e30f));
        s_cur = s_next;
        s_next = m;
    }

    a0 += trans[(T+1)*LP + lane];
    if (lane < LP-32) a1 += trans[(T+1)*LP + 32 + lane];
    float v = rmax32(fmaxf(a0, (lane < LP-32) ? a1 : -1e30f));
    float e = __expf(a0 - v) + ((lane < LP-32) ? __expf(a1 - v) : 0.f);
    #pragma unroll
    for (int o = 16; o; o >>= 1) e += __shfl_xor_sync(~0u, e, o);
    if (lane == 0) loss[b] = g - (v + logf(e));
}

// ---------------------------------------------------------------------------
extern "C" void kernel_launch(void* const* d_in, const int* in_sizes, int n_in,
                              void* d_out, int out_size)
{
    const float* h      = (const float*)d_in[0];
    const int*   lens   = (const int*)d_in[2];
    const int*   labels = (const int*)d_in[3];
    const float* bio    = (const float*)d_in[4];
    const float* W_cat  = (const float*)d_in[5];
    const float* b_cat  = (const float*)d_in[6];
    const float* W_crf  = (const float*)d_in[7];
    const float* b_crf  = (const float*)d_in[8];
    const float* trans  = (const float*)d_in[9];

    float* out = (float*)d_out;            // ner_scores [B,S,LP] then loss [B]
    float* loss = out + (size_t)B * S * LP;

    size_t smem1  = (size_t)(T*H) * sizeof(__nv_bfloat16);  // 75776
    size_t smem4  = (size_t)(S*LP) * sizeof(float);         // 79872

    static int attr_done = 0;
    if (!attr_done) {
        cudaFuncSetAttribute(k1_bio_attn, cudaFuncAttributeMaxDynamicSharedMemorySize, (int)smem1);
        cudaFuncSetAttribute(k2_mma,      cudaFuncAttributeMaxDynamicSharedMemorySize, SMEM_K2);
        cudaFuncSetAttribute(k3_mma,      cudaFuncAttributeMaxDynamicSharedMemorySize, SMEM_K3);
        cudaFuncSetAttribute(k4_crf,      cudaFuncAttributeMaxDynamicSharedMemorySize, (int)smem4);
        attr_done = 1;
    }

    // order chosen so k2 is the 4th launch (profiler capture slot)
    k1_bio_attn<<<BS/16, 256, smem1>>>(h, bio);
    k_bw2<<<dim3(H/32, KSPLIT), 256>>>(bio, W_cat);
    kprep<<<2624, 256>>>(W_cat, W_crf);
    k2_mma<<<dim3(H/KBN, BS/KBM), 256, SMEM_K2>>>(b_cat);
    k3_mma<<<BS/128, 256, SMEM_K3>>>(b_crf, out);
    k4_crf<<<B, 32, smem4>>>(out, labels, lens, trans, loss);
}

// round 16
// speedup vs baseline: 1.0768x; 1.0768x over previous
#include <cuda_runtime.h>
#include <cuda_bf16.h>
#include <cstdint>
#include <math.h>

// Problem constants
#define B   32
#define S   512
#define H   1024
#define T   37
#define LP  39
#define BS  (B*S)          // 16384
#define ZK2 2112           // 1024 (h) + 1024 (h*aware) + 64 (attn pad)
#define KSPLIT 8

// Scratch (device-global)
__device__ __align__(256) __nv_bfloat16 g_Zb[BS * ZK2];  // 66 MiB
__device__ __align__(256) __nv_bfloat16 g_Wt[H * ZK2];   // [n][k]  4.3 MiB
__device__ __align__(256) __nv_bfloat16 g_Yb[BS * H];    // gelu out, bf16, 32 MiB
__device__ __align__(256) __nv_bfloat16 g_W3[64 * H];    // W_crf^T padded, bf16
__device__ __align__(256) float g_BW2p[KSPLIT * T * H];  // bw2 partials, 1.2 MiB

// ===========================================================================
// helpers
// ===========================================================================
__device__ __forceinline__ uint32_t smem_u32(const void* p) {
    uint32_t a;
    asm("{ .reg .u64 t; cvta.to.shared.u64 t, %1; cvt.u32.u64 %0, t; }"
        : "=r"(a) : "l"(p));
    return a;
}
__device__ __forceinline__ void cp16(uint32_t dst, const void* src) {
    asm volatile("cp.async.cg.shared.global [%0], [%1], 16;\n" :: "r"(dst), "l"(src));
}
#define CP_COMMIT() asm volatile("cp.async.commit_group;\n" ::: "memory")
#define CP_WAIT(n)  asm volatile("cp.async.wait_group %0;\n" :: "n"(n) : "memory")

__device__ __forceinline__ float gelu(float v) {
    return 0.5f * v * (1.f + erff(v * 0.70710678118654752f));
}
__device__ __forceinline__ void ldsm4(uint32_t* r, uint32_t addr) {
    asm volatile("ldmatrix.sync.aligned.m8n8.x4.shared.b16 {%0,%1,%2,%3}, [%4];"
        : "=r"(r[0]), "=r"(r[1]), "=r"(r[2]), "=r"(r[3]) : "r"(addr));
}
__device__ __forceinline__ void mma_bf16(
    float* d, const uint32_t* a, uint32_t b0, uint32_t b1)
{
    asm volatile(
        "mma.sync.aligned.m16n8k16.row.col.f32.bf16.bf16.f32 "
        "{%0,%1,%2,%3}, {%4,%5,%6,%7}, {%8,%9}, {%0,%1,%2,%3};"
        : "+f"(d[0]), "+f"(d[1]), "+f"(d[2]), "+f"(d[3])
        : "r"(a[0]), "r"(a[1]), "r"(a[2]), "r"(a[3]), "r"(b0), "r"(b1));
}
__device__ __forceinline__ float rmax32(float x) {
    uint32_t k = __float_as_uint(x);
    k = (k & 0x80000000u) ? ~k : (k | 0x80000000u);
    k = __reduce_max_sync(0xFFFFFFFFu, k);
    return __uint_as_float((k & 0x80000000u) ? (k & 0x7FFFFFFFu) : ~k);
}
__device__ __forceinline__ uint2 pack4bf(float4 v) {
    __nv_bfloat162 p0; p0.x = __float2bfloat16(v.x); p0.y = __float2bfloat16(v.y);
    __nv_bfloat162 p1; p1.x = __float2bfloat16(v.z); p1.y = __float2bfloat16(v.w);
    uint2 r; r.x = *(uint32_t*)&p0; r.y = *(uint32_t*)&p1; return r;
}

// ===========================================================================
// kfused: block-range dispatch.
//   bid [0,1024):      k1 bio-attention (heavy; scheduled first)
//   bid [1024,1280):   k_bw2 partial GEMV (flattened 32 x 8)
//   bid [1280,3392):   weight transposes (Wt 2048 blocks, W3 64 blocks)
// ===========================================================================
__device__ void k1_body(char* dsm, int bid,
    const float* __restrict__ h, const float* __restrict__ bio)
{
    __nv_bfloat16* bioB = (__nv_bfloat16*)dsm;     // [T][H] bf16
    int tid = threadIdx.x;
    for (int i = tid; i < T*H/2; i += 256) {
        float2 v = ((const float2*)bio)[i];
        __nv_bfloat162 p; p.x = __float2bfloat16(v.x); p.y = __float2bfloat16(v.y);
        ((__nv_bfloat162*)bioB)[i] = p;
    }
    __syncthreads();

    int wid = tid >> 5, l = tid & 31;
    int row0 = (bid * 8 + wid) * 2;
    int row1 = row0 + 1;
    const uint2* bB = (const uint2*)bioB;

    uint2 h0p[8], h1p[8];
    {
        const float4* p0 = (const float4*)(h + (size_t)row0 * H);
        const float4* p1 = (const float4*)(h + (size_t)row1 * H);
        __nv_bfloat16* zr0 = g_Zb + (size_t)row0 * ZK2;
        __nv_bfloat16* zr1 = g_Zb + (size_t)row1 * ZK2;
        #pragma unroll
        for (int j = 0; j < 8; j++) {
            h0p[j] = pack4bf(p0[j*32 + l]);
            h1p[j] = pack4bf(p1[j*32 + l]);
            *(uint2*)(zr0 + j*128 + 4*l) = h0p[j];
            *(uint2*)(zr1 + j*128 + 4*l) = h1p[j];
        }
    }

    float v0a = -1e30f, v0b = -1e30f, v1a = -1e30f, v1b = -1e30f;
    const __nv_bfloat162 z2 = __float2bfloat162_rn(0.f);
    for (int t = 0; t < T; t++) {
        const uint2* bt = bB + t*256;
        __nv_bfloat162 a0a = z2, a0b = z2, a1a = z2, a1b = z2;
        #pragma unroll
        for (int j = 0; j < 8; j++) {
            uint2 pk = bt[j*32 + l];
            __nv_bfloat162 b01 = *(__nv_bfloat162*)&pk.x;
            __nv_bfloat162 b23 = *(__nv_bfloat162*)&pk.y;
            a0a = __hfma2(b01, *(__nv_bfloat162*)&h0p[j].x, a0a);
            a0b = __hfma2(b23, *(__nv_bfloat162*)&h0p[j].y, a0b);
            a1a = __hfma2(b01, *(__nv_bfloat162*)&h1p[j].x, a1a);
            a1b = __hfma2(b23, *(__nv_bfloat162*)&h1p[j].y, a1b);
        }
        float2 f0 = __bfloat1622float2(a0a), f0q = __bfloat1622float2(a0b);
        float2 f1 = __bfloat1622float2(a1a), f1q = __bfloat1622float2(a1b);
        float s0 = (f0.x + f0.y) + (f0q.x + f0q.y);
        float s1 = (f1.x + f1.y) + (f1q.x + f1q.y);
        #pragma unroll
        for (int o = 16; o; o >>= 1) {
            s0 += __shfl_xor_sync(~0u, s0, o);
            s1 += __shfl_xor_sync(~0u, s1, o);
        }
        s0 *= 0.03125f; s1 *= 0.03125f;
        if (t < 32) { if (l == t)    { v0a = s0; v1a = s1; } }
        else        { if (l == t-32) { v0b = s0; v1b = s1; } }
    }

    float e0a, e0b, e1a, e1b;
    {
        float m0 = rmax32(fmaxf(v0a, (l < T-32) ? v0b : -1e30f));
        e0a = __expf(v0a - m0);
        e0b = (l < T-32) ? __expf(v0b - m0) : 0.f;
        float ss = e0a + e0b;
        #pragma unroll
        for (int o = 16; o; o >>= 1) ss += __shfl_xor_sync(~0u, ss, o);
        float inv = 1.f / ss; e0a *= inv; e0b *= inv;

        float m1 = rmax32(fmaxf(v1a, (l < T-32) ? v1b : -1e30f));
        e1a = __expf(v1a - m1);
        e1b = (l < T-32) ? __expf(v1b - m1) : 0.f;
        float s1s = e1a + e1b;
        #pragma unroll
        for (int o = 16; o; o >>= 1) s1s += __shfl_xor_sync(~0u, s1s, o);
        float inv1 = 1.f / s1s; e1a *= inv1; e1b *= inv1;
    }

    {
        __nv_bfloat16* zr0 = g_Zb + (size_t)row0 * ZK2;
        __nv_bfloat16* zr1 = g_Zb + (size_t)row1 * ZK2;
        int i0 = 2*l, i1 = 2*l + 1;
        float r0lo0 = __shfl_sync(~0u, e0a, i0 & 31);
        float r0hi0 = __shfl_sync(~0u, e0b, (i0 >= 32) ? (i0 - 32) : 0);
        float r0lo1 = __shfl_sync(~0u, e0a, i1 & 31);
        float r0hi1 = __shfl_sync(~0u, e0b, (i1 >= 32) ? (i1 - 32) : 0);
        float r1lo0 = __shfl_sync(~0u, e1a, i0 & 31);
        float r1hi0 = __shfl_sync(~0u, e1b, (i0 >= 32) ? (i0 - 32) : 0);
        float r1lo1 = __shfl_sync(~0u, e1a, i1 & 31);
        float r1hi1 = __shfl_sync(~0u, e1b, (i1 >= 32) ? (i1 - 32) : 0);
        float a00 = (i0 < 32) ? r0lo0 : r0hi0; if (i0 >= T) a00 = 0.f;
        float a01 = (i1 < 32) ? r0lo1 : r0hi1; if (i1 >= T) a01 = 0.f;
        float a10 = (i0 < 32) ? r1lo0 : r1hi0; if (i0 >= T) a10 = 0.f;
        float a11 = (i1 < 32) ? r1lo1 : r1hi1; if (i1 >= T) a11 = 0.f;
        __nv_bfloat162 q0; q0.x = __float2bfloat16(a00); q0.y = __float2bfloat16(a01);
        __nv_bfloat162 q1; q1.x = __float2bfloat16(a10); q1.y = __float2bfloat16(a11);
        *(uint32_t*)(zr0 + 2048 + 2*l) = *(uint32_t*)&q0;
        *(uint32_t*)(zr1 + 2048 + 2*l) = *(uint32_t*)&q1;
    }

    __nv_bfloat162 aw0[16], aw1[16];
    #pragma unroll
    for (int j = 0; j < 16; j++) { aw0[j] = z2; aw1[j] = z2; }
    for (int t = 0; t < T; t++) {
        float a0f = (t < 32) ? __shfl_sync(~0u, e0a, t) : __shfl_sync(~0u, e0b, t - 32);
        float a1f = (t < 32) ? __shfl_sync(~0u, e1a, t) : __shfl_sync(~0u, e1b, t - 32);
        __nv_bfloat162 a0v = __float2bfloat162_rn(a0f);
        __nv_bfloat162 a1v = __float2bfloat162_rn(a1f);
        const uint2* bt = bB + t*256;
        #pragma unroll
        for (int j = 0; j < 8; j++) {
            uint2 pk = bt[j*32 + l];
            __nv_bfloat162 b01 = *(__nv_bfloat162*)&pk.x;
            __nv_bfloat162 b23 = *(__nv_bfloat162*)&pk.y;
            aw0[2*j]   = __hfma2(b01, a0v, aw0[2*j]);
            aw0[2*j+1] = __hfma2(b23, a0v, aw0[2*j+1]);
            aw1[2*j]   = __hfma2(b01, a1v, aw1[2*j]);
            aw1[2*j+1] = __hfma2(b23, a1v, aw1[2*j+1]);
        }
    }

    {
        __nv_bfloat16* zr0 = g_Zb + (size_t)row0 * ZK2;
        __nv_bfloat16* zr1 = g_Zb + (size_t)row1 * ZK2;
        #pragma unroll
        for (int j = 0; j < 8; j++) {
            __nv_bfloat162 p0x = __hmul2(aw0[2*j],   *(__nv_bfloat162*)&h0p[j].x);
            __nv_bfloat162 p0y = __hmul2(aw0[2*j+1], *(__nv_bfloat162*)&h0p[j].y);
            uint2 pk0; pk0.x = *(uint32_t*)&p0x; pk0.y = *(uint32_t*)&p0y;
            *(uint2*)(zr0 + 1024 + j*128 + 4*l) = pk0;
            __nv_bfloat162 p1x = __hmul2(aw1[2*j],   *(__nv_bfloat162*)&h1p[j].x);
            __nv_bfloat162 p1y = __hmul2(aw1[2*j+1], *(__nv_bfloat162*)&h1p[j].y);
            uint2 pk1; pk1.x = *(uint32_t*)&p1x; pk1.y = *(uint32_t*)&p1y;
            *(uint2*)(zr1 + 1024 + j*128 + 4*l) = pk1;
        }
    }
}

__device__ void bw2_body(char* dsm, int b2,
    const float* __restrict__ bio, const float* __restrict__ W)
{
    float* bioS = (float*)dsm;          // [T][128]
    int tid = threadIdx.x;
    int bx = b2 & 31, by = b2 >> 5;
    int k0 = by * 128;
    for (int i = tid; i < T * 32; i += 256) {
        int t = i >> 5, c = i & 31;
        ((float4*)&bioS[t*128])[c] = ((const float4*)(bio + (size_t)t * H + k0))[c];
    }
    __syncthreads();

    int n = bx * 32 + (tid & 31);
    int th = tid >> 5;
    float acc[5] = {0.f, 0.f, 0.f, 0.f, 0.f};
    #pragma unroll 4
    for (int k = 0; k < 128; k++) {
        float w = W[(size_t)(H + k0 + k) * H + n];
        #pragma unroll
        for (int j = 0; j < 5; j++) {
            int t = th + 8*j;
            float bv = (t < T) ? bioS[t*128 + k] : 0.f;
            acc[j] += bv * w;
        }
    }
    float* pp = g_BW2p + (size_t)by * T * H;
    #pragma unroll
    for (int j = 0; j < 5; j++) {
        int t = th + 8*j;
        if (t < T) pp[t*H + n] = acc[j];
    }
}

__device__ void prep_body(char* dsm, int bid,
    const float* __restrict__ W, const float* __restrict__ Wc)
{
    float* tile = (float*)dsm;          // [32][33]
    int tid = threadIdx.x;
    int tx = tid & 31, ty = tid >> 5;

    if (bid < 2048) {
        int k0 = (bid & 63) * 32;
        int n0 = (bid >> 6) * 32;
        #pragma unroll
        for (int j = 0; j < 32; j += 8) {
            int k = k0 + ty + j;
            int src = (k < H) ? k : (k + H);
            tile[(ty + j)*33 + tx] = W[(size_t)src * H + n0 + tx];
        }
        __syncthreads();
        #pragma unroll
        for (int j = 0; j < 32; j += 8) {
            int n = n0 + ty + j;
            g_Wt[(size_t)n * ZK2 + k0 + tx] = __float2bfloat16(tile[tx*33 + ty + j]);
        }
    } else {
        int b2 = bid - 2048;
        int k0 = (b2 & 31) * 32;
        int t0 = (b2 >> 5) * 32;
        #pragma unroll
        for (int j = 0; j < 32; j += 8) {
            int k = k0 + ty + j, t = t0 + tx;
            tile[(ty + j)*33 + tx] = (t < T) ? Wc[(size_t)k * T + t] : 0.f;
        }
        __syncthreads();
        #pragma unroll
        for (int j = 0; j < 32; j += 8) {
            int t = t0 + ty + j;
            g_W3[(size_t)t * H + k0 + tx] = __float2bfloat16(tile[tx*33 + ty + j]);
        }
    }
}

__global__ __launch_bounds__(256, 2) void kfused(
    const float* __restrict__ h, const float* __restrict__ bio,
    const float* __restrict__ W, const float* __restrict__ Wc)
{
    extern __shared__ __align__(16) char dsm[];
    int bid = blockIdx.x;
    if (bid < 1024)       k1_body(dsm, bid, h, bio);
    else if (bid < 1280)  bw2_body(dsm, bid - 1024, bio, W);
    else                  prep_body(dsm, bid - 1280, W, Wc);
}

// ---------------------------------------------------------------------------
// kfin: g_Wt[n][2048+c] = bf16(sum_s BW2 partial) for c<T else 0 (pads too)
// ---------------------------------------------------------------------------
__global__ __launch_bounds__(256) void kfin()
{
    int idx = blockIdx.x * 256 + threadIdx.x;     // 0 .. H*64-1
    int n = idx >> 6, c = idx & 63;
    float s = 0.f;
    if (c < T) {
        #pragma unroll
        for (int q = 0; q < KSPLIT; q++)
            s += g_BW2p[(size_t)q * T * H + c*H + n];
    }
    g_Wt[(size_t)n * ZK2 + 2048 + c] = __float2bfloat16(s);
}

// ---------------------------------------------------------------------------
// k2: Yb = bf16(gelu(Z @ Wt^T + bc))  bf16 mma, BM=128 BN=128 BK=64,
// warp tile 32x64, 3-stage cp.async, 2 CTAs/SM, single sync/iter (R9 config).
// ---------------------------------------------------------------------------
#define KBM 128
#define KBN 128
#define KBK 64
#define NKI (ZK2/KBK)            // 33
#define STG (KBM*128 + KBN*128)  // 32768 bytes
#define SMEM_K2 (3*STG)          // 98304

__device__ __forceinline__ void k2_load_stage(
    uint32_t sb, int tid, int j, const char* Zb, const char* Wb)
{
    uint32_t base = sb + (j % 3) * STG;
    int kb = j * 128;
    #pragma unroll
    for (int q = 0; q < 8; q++) {
        int idx = tid + 256*q;
        if (q < 4) {
            int m = idx >> 3, c = idx & 7;
            cp16(base + ((m*128 + c*16) ^ ((m & 7) << 4)),
                 Zb + (size_t)m * (ZK2*2) + kb + c*16);
        } else {
            int ci = idx - 1024;
            int n = ci >> 3, c = ci & 7;
            cp16(base + 16384 + ((n*128 + c*16) ^ ((n & 7) << 4)),
                 Wb + (size_t)n * (ZK2*2) + kb + c*16);
        }
    }
}

__global__ __launch_bounds__(256, 2) void k2_mma(const float* __restrict__ bc)
{
    extern __shared__ __align__(16) char smem[];
    uint32_t sb = smem_u32(smem);
    int tid = threadIdx.x, lane = tid & 31, wid = tid >> 5;
    int wm = wid & 3, wn = wid >> 2;
    int row0 = blockIdx.y * KBM, n0 = blockIdx.x * KBN;

    const char* Zb = (const char*)g_Zb + (size_t)row0 * (ZK2*2);
    const char* Wb = (const char*)g_Wt + (size_t)n0   * (ZK2*2);

    float acc[2][8][4];
    #pragma unroll
    for (int mt = 0; mt < 2; mt++)
        #pragma unroll
        for (int nt = 0; nt < 8; nt++)
            #pragma unroll
            for (int q = 0; q < 4; q++) acc[mt][nt][q] = 0.f;

    k2_load_stage(sb, tid, 0, Zb, Wb); CP_COMMIT();
    k2_load_stage(sb, tid, 1, Zb, Wb); CP_COMMIT();

    int r15 = lane & 15;
    int hb  = (lane >> 4) << 4;

    for (int i = 0; i < NKI; i++) {
        CP_WAIT(1);
        __syncthreads();

        uint32_t Ab = sb + (i % 3) * STG;
        uint32_t Bb = Ab + 16384;
        #pragma unroll
        for (int kk = 0; kk < 4; kk++) {
            int kbyte = kk*32 + hb;
            uint32_t a[2][4];
            #pragma unroll
            for (int mt = 0; mt < 2; mt++) {
                int rr = wm*32 + mt*16 + r15;
                ldsm4(a[mt], Ab + rr*128 + (kbyte ^ ((rr & 7) << 4)));
            }
            #pragma unroll
            for (int ntp = 0; ntp < 4; ntp++) {
                int nr = wn*64 + ntp*16 + r15;
                uint32_t b[4];
                ldsm4(b, Bb + nr*128 + (kbyte ^ ((nr & 7) << 4)));
                #pragma unroll
                for (int mt = 0; mt < 2; mt++) {
                    mma_bf16(acc[mt][2*ntp],   a[mt], b[0], b[2]);
                    mma_bf16(acc[mt][2*ntp+1], a[mt], b[1], b[3]);
                }
            }
        }

        int j = i + 2;
        if (j < NKI) k2_load_stage(sb, tid, j, Zb, Wb);
        CP_COMMIT();
    }

    int g = lane >> 2, t4 = lane & 3;
    #pragma unroll
    for (int mt = 0; mt < 2; mt++) {
        #pragma unroll
        for (int nt = 0; nt < 8; nt++) {
            int r0 = row0 + wm*32 + mt*16 + g;
            int c  = n0 + wn*64 + nt*8 + 2*t4;
            float b0v = __ldg(bc + c), b1v = __ldg(bc + c + 1);
            __nv_bfloat162 o0, o1;
            o0.x = __float2bfloat16(gelu(acc[mt][nt][0] + b0v));
            o0.y = __float2bfloat16(gelu(acc[mt][nt][1] + b1v));
            o1.x = __float2bfloat16(gelu(acc[mt][nt][2] + b0v));
            o1.y = __float2bfloat16(gelu(acc[mt][nt][3] + b1v));
            *(uint32_t*)(g_Yb + (size_t)r0 * H + c) = *(uint32_t*)&o0;
            *(uint32_t*)(g_Yb + (size_t)(r0 + 8) * H + c) = *(uint32_t*)&o1;
        }
    }
}

// ---------------------------------------------------------------------------
// k3: logits = Yb @ W3^T + b_crf -> ner_scores (+ pads), via bf16 mma.
// ---------------------------------------------------------------------------
#define STG3 (128*128 + 64*128)   // 24576 bytes
#define SMEM_K3 (3*STG3)          // 73728
#define NKI3 (H/64)               // 16

__device__ __forceinline__ void k3_load_stage(
    uint32_t sb, int tid, int j, const char* Yb)
{
    uint32_t base = sb + (j % 3) * STG3;
    int kb = j * 128;
    #pragma unroll
    for (int q = 0; q < 6; q++) {
        int idx = tid + 256*q;
        if (q < 4) {
            int m = idx >> 3, c = idx & 7;
            cp16(base + ((m*128 + c*16) ^ ((m & 7) << 4)),
                 Yb + (size_t)m * (H*2) + kb + c*16);
        } else {
            int ci = idx - 1024;
            int n = ci >> 3, c = ci & 7;
            cp16(base + 16384 + ((n*128 + c*16) ^ ((n & 7) << 4)),
                 (const char*)g_W3 + (size_t)n * (H*2) + kb + c*16);
        }
    }
}

__global__ __launch_bounds__(256, 2) void k3_mma(
    const float* __restrict__ bcrf, float* __restrict__ out)
{
    extern __shared__ __align__(16) char smem[];
    uint32_t sb = smem_u32(smem);
    int tid = threadIdx.x, lane = tid & 31, wid = tid >> 5;
    int wm = wid & 3, wn = wid >> 2;          // 4 x 2
    int row0 = blockIdx.x * 128;

    const char* Yb = (const char*)g_Yb + (size_t)row0 * (H*2);

    float acc[2][4][4];
    #pragma unroll
    for (int mt = 0; mt < 2; mt++)
        #pragma unroll
        for (int nt = 0; nt < 4; nt++)
            #pragma unroll
            for (int q = 0; q < 4; q++) acc[mt][nt][q] = 0.f;

    k3_load_stage(sb, tid, 0, Yb); CP_COMMIT();
    k3_load_stage(sb, tid, 1, Yb); CP_COMMIT();

    int r15 = lane & 15;
    int hb  = (lane >> 4) << 4;

    for (int i = 0; i < NKI3; i++) {
        CP_WAIT(1);
        __syncthreads();

        uint32_t Ab = sb + (i % 3) * STG3;
        uint32_t Bb = Ab + 16384;
        #pragma unroll
        for (int kk = 0; kk < 4; kk++) {
            int kbyte = kk*32 + hb;
            uint32_t a[2][4];
            #pragma unroll
            for (int mt = 0; mt < 2; mt++) {
                int rr = wm*32 + mt*16 + r15;
                ldsm4(a[mt], Ab + rr*128 + (kbyte ^ ((rr & 7) << 4)));
            }
            #pragma unroll
            for (int np = 0; np < 2; np++) {
                int nr = wn*32 + np*16 + r15;
                uint32_t b[4];
                ldsm4(b, Bb + nr*128 + (kbyte ^ ((nr & 7) << 4)));
                #pragma unroll
                for (int mt = 0; mt < 2; mt++) {
                    mma_bf16(acc[mt][2*np],   a[mt], b[0], b[2]);
                    mma_bf16(acc[mt][2*np+1], a[mt], b[1], b[3]);
                }
            }
        }

        int j = i + 2;
        if (j < NKI3) k3_load_stage(sb, tid, j, Yb);
        CP_COMMIT();
    }

    int g = lane >> 2, t4 = lane & 3;
    #pragma unroll
    for (int mt = 0; mt < 2; mt++) {
        int r = row0 + wm*32 + mt*16 + g;
        #pragma unroll
        for (int nt = 0; nt < 4; nt++) {
            int c0 = wn*32 + nt*8 + 2*t4, c1 = c0 + 1;
            if (c0 < T) {
                float bv = __ldg(bcrf + c0);
                out[(size_t)r*LP + c0]     = acc[mt][nt][0] + bv;
                out[(size_t)(r+8)*LP + c0] = acc[mt][nt][2] + bv;
            }
            if (c1 < T) {
                float bv = __ldg(bcrf + c1);
                out[(size_t)r*LP + c1]     = acc[mt][nt][1] + bv;
                out[(size_t)(r+8)*LP + c1] = acc[mt][nt][3] + bv;
            }
        }
        if (wn == 1 && t4 == 0) {
            out[(size_t)r*LP + 37] = -10000.f;  out[(size_t)r*LP + 38] = -10000.f;
            out[(size_t)(r+8)*LP + 37] = -10000.f; out[(size_t)(r+8)*LP + 38] = -10000.f;
        }
    }
}

// ---------------------------------------------------------------------------
// k4: CRF loglik. One warp per batch; lagged-shift LSE scan (exact).
// ---------------------------------------------------------------------------
__global__ __launch_bounds__(32) void k4_crf(
    const float* __restrict__ scores, const int* __restrict__ labels,
    const int* __restrict__ lens, const float* __restrict__ trans,
    float* __restrict__ loss)
{
    extern __shared__ float sc[];
    int b = blockIdx.x;
    int lane = threadIdx.x;
    int len = lens[b];
    const int* lab = labels + b*S;

    {
        uint32_t sbase = smem_u32(sc);
        const float4* src = (const float4*)(scores + (size_t)b * S * LP);
        for (int i = lane; i < S*LP/4; i += 32)
            cp16(sbase + i*16, src + i);
        CP_COMMIT();
        CP_WAIT(0);
        __syncwarp();
    }

    float ET0[LP], ET1[LP], maxT0 = -1e30f, maxT1 = -1e30f;
    {
        const float* tr = trans + lane*LP;
        #pragma unroll
        for (int f = 0; f < LP; f++) maxT0 = fmaxf(maxT0, tr[f]);
        #pragma unroll
        for (int f = 0; f < LP; f++) ET0[f] = __expf(tr[f] - maxT0);
    }
    if (lane < LP-32) {
        const float* tr = trans + (32+lane)*LP;
        #pragma unroll
        for (int f = 0; f < LP; f++) maxT1 = fmaxf(maxT1, tr[f]);
        #pragma unroll
        for (int f = 0; f < LP; f++) ET1[f] = __expf(tr[f] - maxT1);
    }

    float g = 0.f;
    for (int s2 = lane; s2 < len; s2 += 32) g += sc[s2*LP + lab[s2]];
    for (int i = lane; i <= len; i += 32) {
        int frm = (i == 0)   ? T       : lab[i-1];
        int to  = (i == len) ? (T + 1) : lab[i];
        g += trans[to*LP + frm];
    }
    #pragma unroll
    for (int o = 16; o; o >>= 1) g += __shfl_xor_sync(~0u, g, o);

    float a0 = -100.f;
    float a1 = (lane == (T - 32)) ? 0.f : -100.f;
    float s_cur = 0.f, s_next = 0.f;

    for (int t = 0; t < len; t++) {
        float e0 = __expf(a0 - s_cur);
        float e1 = (lane < LP-32) ? __expf(a1 - s_cur) : 0.f;
        float s0a = 0.f, s0b = 0.f, s1a = 0.f, s1b = 0.f;
        #pragma unroll
        for (int f = 0; f < 32; f += 2) {
            float ea = __shfl_sync(~0u, e0, f);
            float eb = __shfl_sync(~0u, e0, f+1);
            s0a += ea*ET0[f];   s0b += eb*ET0[f+1];
            s1a += ea*ET1[f];   s1b += eb*ET1[f+1];
        }
        #pragma unroll
        for (int f = 0; f < LP-32; f++) {
            float ea = __shfl_sync(~0u, e1, f);
            s0a += ea*ET0[32+f];
            s1a += ea*ET1[32+f];
        }
        a0 = sc[t*LP + lane] + s_cur + maxT0 + __logf(s0a + s0b);
        if (lane < LP-32)
            a1 = sc[t*LP + 32 + lane] + s_cur + maxT1 + __logf(s1a + s1b);
        float m = rmax32(fmaxf(a0, (lane < LP-32) ? a1 : -1e30f));
        s_cur = s_next;
        s_next = m;
    }

    a0 += trans[(T+1)*LP + lane];
    if (lane < LP-32) a1 += trans[(T+1)*LP + 32 + lane];
    float v = rmax32(fmaxf(a0, (lane < LP-32) ? a1 : -1e30f));
    float e = __expf(a0 - v) + ((lane < LP-32) ? __expf(a1 - v) : 0.f);
    #pragma unroll
    for (int o = 16; o; o >>= 1) e += __shfl_xor_sync(~0u, e, o);
    if (lane == 0) loss[b] = g - (v + logf(e));
}

// ---------------------------------------------------------------------------
extern "C" void kernel_launch(void* const* d_in, const int* in_sizes, int n_in,
                              void* d_out, int out_size)
{
    const float* h      = (const float*)d_in[0];
    const int*   lens   = (const int*)d_in[2];
    const int*   labels = (const int*)d_in[3];
    const float* bio    = (const float*)d_in[4];
    const float* W_cat  = (const float*)d_in[5];
    const float* b_cat  = (const float*)d_in[6];
    const float* W_crf  = (const float*)d_in[7];
    const float* b_crf  = (const float*)d_in[8];
    const float* trans  = (const float*)d_in[9];

    float* out = (float*)d_out;            // ner_scores [B,S,LP] then loss [B]
    float* loss = out + (size_t)B * S * LP;

    size_t smemF  = (size_t)(T*H) * sizeof(__nv_bfloat16);  // 75776 (max of branches)
    size_t smem4  = (size_t)(S*LP) * sizeof(float);         // 79872

    static int attr_done = 0;
    if (!attr_done) {
        cudaFuncSetAttribute(kfused, cudaFuncAttributeMaxDynamicSharedMemorySize, (int)smemF);
        cudaFuncSetAttribute(k2_mma, cudaFuncAttributeMaxDynamicSharedMemorySize, SMEM_K2);
        cudaFuncSetAttribute(k3_mma, cudaFuncAttributeMaxDynamicSharedMemorySize, SMEM_K3);
        cudaFuncSetAttribute(k4_crf, cudaFuncAttributeMaxDynamicSharedMemorySize, (int)smem4);
        attr_done = 1;
    }

    kfused<<<3392, 256, smemF>>>(h, bio, W_cat, W_crf);
    kfin<<<H*64/256, 256>>>();
    k2_mma<<<dim3(H/KBN, BS/KBM), 256, SMEM_K2>>>(b_cat);
    k3_mma<<<BS/128, 256, SMEM_K3>>>(b_crf, out);
    k4_crf<<<B, 32, smem4>>>(out, labels, lens, trans, loss);
}

// round 17
// speedup vs baseline: 1.0975x; 1.0193x over previous
#include <cuda_runtime.h>
#include <cuda_bf16.h>
#include <cstdint>
#include <math.h>

// Problem constants
#define B   32
#define S   512
#define H   1024
#define T   37
#define LP  39
#define BS  (B*S)          // 16384
#define ZK2 2112           // 1024 (h) + 1024 (h*aware) + 64 (attn pad)
#define KSPLIT 8

// Scratch (device-global)
__device__ __align__(256) __nv_bfloat16 g_Zb[BS * ZK2];  // 66 MiB
__device__ __align__(256) __nv_bfloat16 g_Wt[H * ZK2];   // [n][k]  4.3 MiB
__device__ __align__(256) __nv_bfloat16 g_Yb[BS * H];    // gelu out, bf16, 32 MiB
__device__ __align__(256) __nv_bfloat16 g_W3[64 * H];    // W_crf^T padded, bf16
__device__ __align__(256) float g_BW2p[KSPLIT * T * H];  // bw2 partials, 1.2 MiB

// ===========================================================================
// helpers
// ===========================================================================
__device__ __forceinline__ uint32_t smem_u32(const void* p) {
    uint32_t a;
    asm("{ .reg .u64 t; cvta.to.shared.u64 t, %1; cvt.u32.u64 %0, t; }"
        : "=r"(a) : "l"(p));
    return a;
}
__device__ __forceinline__ void cp16(uint32_t dst, const void* src) {
    asm volatile("cp.async.cg.shared.global [%0], [%1], 16;\n" :: "r"(dst), "l"(src));
}
#define CP_COMMIT() asm volatile("cp.async.commit_group;\n" ::: "memory")
#define CP_WAIT(n)  asm volatile("cp.async.wait_group %0;\n" :: "n"(n) : "memory")

__device__ __forceinline__ float gelu(float v) {
    return 0.5f * v * (1.f + erff(v * 0.70710678118654752f));
}
__device__ __forceinline__ void ldsm4(uint32_t* r, uint32_t addr) {
    asm volatile("ldmatrix.sync.aligned.m8n8.x4.shared.b16 {%0,%1,%2,%3}, [%4];"
        : "=r"(r[0]), "=r"(r[1]), "=r"(r[2]), "=r"(r[3]) : "r"(addr));
}
__device__ __forceinline__ void mma_bf16(
    float* d, const uint32_t* a, uint32_t b0, uint32_t b1)
{
    asm volatile(
        "mma.sync.aligned.m16n8k16.row.col.f32.bf16.bf16.f32 "
        "{%0,%1,%2,%3}, {%4,%5,%6,%7}, {%8,%9}, {%0,%1,%2,%3};"
        : "+f"(d[0]), "+f"(d[1]), "+f"(d[2]), "+f"(d[3])
        : "r"(a[0]), "r"(a[1]), "r"(a[2]), "r"(a[3]), "r"(b0), "r"(b1));
}
__device__ __forceinline__ float rmax32(float x) {
    uint32_t k = __float_as_uint(x);
    k = (k & 0x80000000u) ? ~k : (k | 0x80000000u);
    k = __reduce_max_sync(0xFFFFFFFFu, k);
    return __uint_as_float((k & 0x80000000u) ? (k & 0x7FFFFFFFu) : ~k);
}
__device__ __forceinline__ uint2 pack4bf(float4 v) {
    __nv_bfloat162 p0; p0.x = __float2bfloat16(v.x); p0.y = __float2bfloat16(v.y);
    __nv_bfloat162 p1; p1.x = __float2bfloat16(v.z); p1.y = __float2bfloat16(v.w);
    uint2 r; r.x = *(uint32_t*)&p0; r.y = *(uint32_t*)&p1; return r;
}

// ===========================================================================
// kfused: block-range dispatch.
//   bid [0,1024):      k1 bio-attention (heavy; scheduled first)
//   bid [1024,1280):   k_bw2 partial GEMV (flattened 32 x 8)
//   bid [1280,3392):   weight transposes (Wt 2048 blocks, W3 64 blocks)
// ===========================================================================
__device__ void k1_body(char* dsm, int bid,
    const float* __restrict__ h, const float* __restrict__ bio)
{
    __nv_bfloat16* bioB = (__nv_bfloat16*)dsm;     // [T][H] bf16
    int tid = threadIdx.x;
    for (int i = tid; i < T*H/2; i += 256) {
        float2 v = ((const float2*)bio)[i];
        __nv_bfloat162 p; p.x = __float2bfloat16(v.x); p.y = __float2bfloat16(v.y);
        ((__nv_bfloat162*)bioB)[i] = p;
    }
    __syncthreads();

    int wid = tid >> 5, l = tid & 31;
    int row0 = (bid * 8 + wid) * 2;
    int row1 = row0 + 1;
    const uint2* bB = (const uint2*)bioB;

    uint2 h0p[8], h1p[8];
    {
        const float4* p0 = (const float4*)(h + (size_t)row0 * H);
        const float4* p1 = (const float4*)(h + (size_t)row1 * H);
        __nv_bfloat16* zr0 = g_Zb + (size_t)row0 * ZK2;
        __nv_bfloat16* zr1 = g_Zb + (size_t)row1 * ZK2;
        #pragma unroll
        for (int j = 0; j < 8; j++) {
            h0p[j] = pack4bf(p0[j*32 + l]);
            h1p[j] = pack4bf(p1[j*32 + l]);
            *(uint2*)(zr0 + j*128 + 4*l) = h0p[j];
            *(uint2*)(zr1 + j*128 + 4*l) = h1p[j];
        }
    }

    // ---- phase A: scores, t unrolled x4 (interleaved shfl chains) ----
    float v0a = -1e30f, v0b = -1e30f, v1a = -1e30f, v1b = -1e30f;
    const __nv_bfloat162 z2 = __float2bfloat162_rn(0.f);
    for (int t0 = 0; t0 < 36; t0 += 4) {
        float s0[4], s1[4];
        #pragma unroll
        for (int tt = 0; tt < 4; tt++) {
            const uint2* bt = bB + (t0 + tt)*256;
            __nv_bfloat162 a0a = z2, a0b = z2, a1a = z2, a1b = z2;
            #pragma unroll
            for (int j = 0; j < 8; j++) {
                uint2 pk = bt[j*32 + l];
                __nv_bfloat162 b01 = *(__nv_bfloat162*)&pk.x;
                __nv_bfloat162 b23 = *(__nv_bfloat162*)&pk.y;
                a0a = __hfma2(b01, *(__nv_bfloat162*)&h0p[j].x, a0a);
                a0b = __hfma2(b23, *(__nv_bfloat162*)&h0p[j].y, a0b);
                a1a = __hfma2(b01, *(__nv_bfloat162*)&h1p[j].x, a1a);
                a1b = __hfma2(b23, *(__nv_bfloat162*)&h1p[j].y, a1b);
            }
            float2 f0 = __bfloat1622float2(a0a), f0q = __bfloat1622float2(a0b);
            float2 f1 = __bfloat1622float2(a1a), f1q = __bfloat1622float2(a1b);
            s0[tt] = (f0.x + f0.y) + (f0q.x + f0q.y);
            s1[tt] = (f1.x + f1.y) + (f1q.x + f1q.y);
        }
        #pragma unroll
        for (int o = 16; o; o >>= 1) {
            #pragma unroll
            for (int tt = 0; tt < 4; tt++) {
                s0[tt] += __shfl_xor_sync(~0u, s0[tt], o);
                s1[tt] += __shfl_xor_sync(~0u, s1[tt], o);
            }
        }
        if (t0 < 32) {
            #pragma unroll
            for (int tt = 0; tt < 4; tt++)
                if (l == t0 + tt) { v0a = s0[tt]*0.03125f; v1a = s1[tt]*0.03125f; }
        } else {
            #pragma unroll
            for (int tt = 0; tt < 4; tt++)
                if (l == t0 + tt - 32) { v0b = s0[tt]*0.03125f; v1b = s1[tt]*0.03125f; }
        }
    }
    {   // t = 36
        const uint2* bt = bB + 36*256;
        __nv_bfloat162 a0a = z2, a0b = z2, a1a = z2, a1b = z2;
        #pragma unroll
        for (int j = 0; j < 8; j++) {
            uint2 pk = bt[j*32 + l];
            __nv_bfloat162 b01 = *(__nv_bfloat162*)&pk.x;
            __nv_bfloat162 b23 = *(__nv_bfloat162*)&pk.y;
            a0a = __hfma2(b01, *(__nv_bfloat162*)&h0p[j].x, a0a);
            a0b = __hfma2(b23, *(__nv_bfloat162*)&h0p[j].y, a0b);
            a1a = __hfma2(b01, *(__nv_bfloat162*)&h1p[j].x, a1a);
            a1b = __hfma2(b23, *(__nv_bfloat162*)&h1p[j].y, a1b);
        }
        float2 f0 = __bfloat1622float2(a0a), f0q = __bfloat1622float2(a0b);
        float2 f1 = __bfloat1622float2(a1a), f1q = __bfloat1622float2(a1b);
        float s0 = (f0.x + f0.y) + (f0q.x + f0q.y);
        float s1 = (f1.x + f1.y) + (f1q.x + f1q.y);
        #pragma unroll
        for (int o = 16; o; o >>= 1) {
            s0 += __shfl_xor_sync(~0u, s0, o);
            s1 += __shfl_xor_sync(~0u, s1, o);
        }
        if (l == 4) { v0b = s0*0.03125f; v1b = s1*0.03125f; }
    }

    float e0a, e0b, e1a, e1b;
    {
        float m0 = rmax32(fmaxf(v0a, (l < T-32) ? v0b : -1e30f));
        e0a = __expf(v0a - m0);
        e0b = (l < T-32) ? __expf(v0b - m0) : 0.f;
        float ss = e0a + e0b;
        #pragma unroll
        for (int o = 16; o; o >>= 1) ss += __shfl_xor_sync(~0u, ss, o);
        float inv = 1.f / ss; e0a *= inv; e0b *= inv;

        float m1 = rmax32(fmaxf(v1a, (l < T-32) ? v1b : -1e30f));
        e1a = __expf(v1a - m1);
        e1b = (l < T-32) ? __expf(v1b - m1) : 0.f;
        float s1s = e1a + e1b;
        #pragma unroll
        for (int o = 16; o; o >>= 1) s1s += __shfl_xor_sync(~0u, s1s, o);
        float inv1 = 1.f / s1s; e1a *= inv1; e1b *= inv1;
    }

    {
        __nv_bfloat16* zr0 = g_Zb + (size_t)row0 * ZK2;
        __nv_bfloat16* zr1 = g_Zb + (size_t)row1 * ZK2;
        int i0 = 2*l, i1 = 2*l + 1;
        float r0lo0 = __shfl_sync(~0u, e0a, i0 & 31);
        float r0hi0 = __shfl_sync(~0u, e0b, (i0 >= 32) ? (i0 - 32) : 0);
        float r0lo1 = __shfl_sync(~0u, e0a, i1 & 31);
        float r0hi1 = __shfl_sync(~0u, e0b, (i1 >= 32) ? (i1 - 32) : 0);
        float r1lo0 = __shfl_sync(~0u, e1a, i0 & 31);
        float r1hi0 = __shfl_sync(~0u, e1b, (i0 >= 32) ? (i0 - 32) : 0);
        float r1lo1 = __shfl_sync(~0u, e1a, i1 & 31);
        float r1hi1 = __shfl_sync(~0u, e1b, (i1 >= 32) ? (i1 - 32) : 0);
        float a00 = (i0 < 32) ? r0lo0 : r0hi0; if (i0 >= T) a00 = 0.f;
        float a01 = (i1 < 32) ? r0lo1 : r0hi1; if (i1 >= T) a01 = 0.f;
        float a10 = (i0 < 32) ? r1lo0 : r1hi0; if (i0 >= T) a10 = 0.f;
        float a11 = (i1 < 32) ? r1lo1 : r1hi1; if (i1 >= T) a11 = 0.f;
        __nv_bfloat162 q0; q0.x = __float2bfloat16(a00); q0.y = __float2bfloat16(a01);
        __nv_bfloat162 q1; q1.x = __float2bfloat16(a10); q1.y = __float2bfloat16(a11);
        *(uint32_t*)(zr0 + 2048 + 2*l) = *(uint32_t*)&q0;
        *(uint32_t*)(zr1 + 2048 + 2*l) = *(uint32_t*)&q1;
    }

    __nv_bfloat162 aw0[16], aw1[16];
    #pragma unroll
    for (int j = 0; j < 16; j++) { aw0[j] = z2; aw1[j] = z2; }
    for (int t = 0; t < T; t++) {
        float a0f = (t < 32) ? __shfl_sync(~0u, e0a, t) : __shfl_sync(~0u, e0b, t - 32);
        float a1f = (t < 32) ? __shfl_sync(~0u, e1a, t) : __shfl_sync(~0u, e1b, t - 32);
        __nv_bfloat162 a0v = __float2bfloat162_rn(a0f);
        __nv_bfloat162 a1v = __float2bfloat162_rn(a1f);
        const uint2* bt = bB + t*256;
        #pragma unroll
        for (int j = 0; j < 8; j++) {
            uint2 pk = bt[j*32 + l];
            __nv_bfloat162 b01 = *(__nv_bfloat162*)&pk.x;
            __nv_bfloat162 b23 = *(__nv_bfloat162*)&pk.y;
            aw0[2*j]   = __hfma2(b01, a0v, aw0[2*j]);
            aw0[2*j+1] = __hfma2(b23, a0v, aw0[2*j+1]);
            aw1[2*j]   = __hfma2(b01, a1v, aw1[2*j]);
            aw1[2*j+1] = __hfma2(b23, a1v, aw1[2*j+1]);
        }
    }

    {
        __nv_bfloat16* zr0 = g_Zb + (size_t)row0 * ZK2;
        __nv_bfloat16* zr1 = g_Zb + (size_t)row1 * ZK2;
        #pragma unroll
        for (int j = 0; j < 8; j++) {
            __nv_bfloat162 p0x = __hmul2(aw0[2*j],   *(__nv_bfloat162*)&h0p[j].x);
            __nv_bfloat162 p0y = __hmul2(aw0[2*j+1], *(__nv_bfloat162*)&h0p[j].y);
            uint2 pk0; pk0.x = *(uint32_t*)&p0x; pk0.y = *(uint32_t*)&p0y;
            *(uint2*)(zr0 + 1024 + j*128 + 4*l) = pk0;
            __nv_bfloat162 p1x = __hmul2(aw1[2*j],   *(__nv_bfloat162*)&h1p[j].x);
            __nv_bfloat162 p1y = __hmul2(aw1[2*j+1], *(__nv_bfloat162*)&h1p[j].y);
            uint2 pk1; pk1.x = *(uint32_t*)&p1x; pk1.y = *(uint32_t*)&p1y;
            *(uint2*)(zr1 + 1024 + j*128 + 4*l) = pk1;
        }
    }
}

__device__ void bw2_body(char* dsm, int b2,
    const float* __restrict__ bio, const float* __restrict__ W)
{
    float* bioS = (float*)dsm;          // [T][128]
    int tid = threadIdx.x;
    int bx = b2 & 31, by = b2 >> 5;
    int k0 = by * 128;
    for (int i = tid; i < T * 32; i += 256) {
        int t = i >> 5, c = i & 31;
        ((float4*)&bioS[t*128])[c] = ((const float4*)(bio + (size_t)t * H + k0))[c];
    }
    __syncthreads();

    int n = bx * 32 + (tid & 31);
    int th = tid >> 5;
    float acc[5] = {0.f, 0.f, 0.f, 0.f, 0.f};
    #pragma unroll 4
    for (int k = 0; k < 128; k++) {
        float w = W[(size_t)(H + k0 + k) * H + n];
        #pragma unroll
        for (int j = 0; j < 5; j++) {
            int t = th + 8*j;
            float bv = (t < T) ? bioS[t*128 + k] : 0.f;
            acc[j] += bv * w;
        }
    }
    float* pp = g_BW2p + (size_t)by * T * H;
    #pragma unroll
    for (int j = 0; j < 5; j++) {
        int t = th + 8*j;
        if (t < T) pp[t*H + n] = acc[j];
    }
}

__device__ void prep_body(char* dsm, int bid,
    const float* __restrict__ W, const float* __restrict__ Wc)
{
    float* tile = (float*)dsm;          // [32][33]
    int tid = threadIdx.x;
    int tx = tid & 31, ty = tid >> 5;

    if (bid < 2048) {
        int k0 = (bid & 63) * 32;
        int n0 = (bid >> 6) * 32;
        #pragma unroll
        for (int j = 0; j < 32; j += 8) {
            int k = k0 + ty + j;
            int src = (k < H) ? k : (k + H);
            tile[(ty + j)*33 + tx] = W[(size_t)src * H + n0 + tx];
        }
        __syncthreads();
        #pragma unroll
        for (int j = 0; j < 32; j += 8) {
            int n = n0 + ty + j;
            g_Wt[(size_t)n * ZK2 + k0 + tx] = __float2bfloat16(tile[tx*33 + ty + j]);
        }
    } else {
        int b2 = bid - 2048;
        int k0 = (b2 & 31) * 32;
        int t0 = (b2 >> 5) * 32;
        #pragma unroll
        for (int j = 0; j < 32; j += 8) {
            int k = k0 + ty + j, t = t0 + tx;
            tile[(ty + j)*33 + tx] = (t < T) ? Wc[(size_t)k * T + t] : 0.f;
        }
        __syncthreads();
        #pragma unroll
        for (int j = 0; j < 32; j += 8) {
            int t = t0 + ty + j;
            g_W3[(size_t)t * H + k0 + tx] = __float2bfloat16(tile[tx*33 + ty + j]);
        }
    }
}

__global__ __launch_bounds__(256, 2) void kfused(
    const float* __restrict__ h, const float* __restrict__ bio,
    const float* __restrict__ W, const float* __restrict__ Wc)
{
    extern __shared__ __align__(16) char dsm[];
    int bid = blockIdx.x;
    if (bid < 1024)       k1_body(dsm, bid, h, bio);
    else if (bid < 1280)  bw2_body(dsm, bid - 1024, bio, W);
    else                  prep_body(dsm, bid - 1280, W, Wc);
}

// ---------------------------------------------------------------------------
// kfin: g_Wt[n][2048+c] = bf16(sum_s BW2 partial) for c<T else 0 (pads too)
// ---------------------------------------------------------------------------
__global__ __launch_bounds__(256) void kfin()
{
    int idx = blockIdx.x * 256 + threadIdx.x;     // 0 .. H*64-1
    int n = idx >> 6, c = idx & 63;
    float s = 0.f;
    if (c < T) {
        #pragma unroll
        for (int q = 0; q < KSPLIT; q++)
            s += g_BW2p[(size_t)q * T * H + c*H + n];
    }
    g_Wt[(size_t)n * ZK2 + 2048 + c] = __float2bfloat16(s);
}

// ---------------------------------------------------------------------------
// k2: Yb = bf16(gelu(Z @ Wt^T + bc))  bf16 mma, BM=128 BN=128 BK=64,
// warp tile 32x64, 3-stage cp.async, 2 CTAs/SM, single sync/iter (R9 config).
// ---------------------------------------------------------------------------
#define KBM 128
#define KBN 128
#define KBK 64
#define NKI (ZK2/KBK)            // 33
#define STG (KBM*128 + KBN*128)  // 32768 bytes
#define SMEM_K2 (3*STG)          // 98304

__device__ __forceinline__ void k2_load_stage(
    uint32_t sb, int tid, int j, const char* Zb, const char* Wb)
{
    uint32_t base = sb + (j % 3) * STG;
    int kb = j * 128;
    #pragma unroll
    for (int q = 0; q < 8; q++) {
        int idx = tid + 256*q;
        if (q < 4) {
            int m = idx >> 3, c = idx & 7;
            cp16(base + ((m*128 + c*16) ^ ((m & 7) << 4)),
                 Zb + (size_t)m * (ZK2*2) + kb + c*16);
        } else {
            int ci = idx - 1024;
            int n = ci >> 3, c = ci & 7;
            cp16(base + 16384 + ((n*128 + c*16) ^ ((n & 7) << 4)),
                 Wb + (size_t)n * (ZK2*2) + kb + c*16);
        }
    }
}

__global__ __launch_bounds__(256, 2) void k2_mma(const float* __restrict__ bc)
{
    extern __shared__ __align__(16) char smem[];
    uint32_t sb = smem_u32(smem);
    int tid = threadIdx.x, lane = tid & 31, wid = tid >> 5;
    int wm = wid & 3, wn = wid >> 2;
    int row0 = blockIdx.y * KBM, n0 = blockIdx.x * KBN;

    const char* Zb = (const char*)g_Zb + (size_t)row0 * (ZK2*2);
    const char* Wb = (const char*)g_Wt + (size_t)n0   * (ZK2*2);

    float acc[2][8][4];
    #pragma unroll
    for (int mt = 0; mt < 2; mt++)
        #pragma unroll
        for (int nt = 0; nt < 8; nt++)
            #pragma unroll
            for (int q = 0; q < 4; q++) acc[mt][nt][q] = 0.f;

    k2_load_stage(sb, tid, 0, Zb, Wb); CP_COMMIT();
    k2_load_stage(sb, tid, 1, Zb, Wb); CP_COMMIT();

    int r15 = lane & 15;
    int hb  = (lane >> 4) << 4;

    for (int i = 0; i < NKI; i++) {
        CP_WAIT(1);
        __syncthreads();

        uint32_t Ab = sb + (i % 3) * STG;
        uint32_t Bb = Ab + 16384;
        #pragma unroll
        for (int kk = 0; kk < 4; kk++) {
            int kbyte = kk*32 + hb;
            uint32_t a[2][4];
            #pragma unroll
            for (int mt = 0; mt < 2; mt++) {
                int rr = wm*32 + mt*16 + r15;
                ldsm4(a[mt], Ab + rr*128 + (kbyte ^ ((rr & 7) << 4)));
            }
            #pragma unroll
            for (int ntp = 0; ntp < 4; ntp++) {
                int nr = wn*64 + ntp*16 + r15;
                uint32_t b[4];
                ldsm4(b, Bb + nr*128 + (kbyte ^ ((nr & 7) << 4)));
                #pragma unroll
                for (int mt = 0; mt < 2; mt++) {
                    mma_bf16(acc[mt][2*ntp],   a[mt], b[0], b[2]);
                    mma_bf16(acc[mt][2*ntp+1], a[mt], b[1], b[3]);
                }
            }
        }

        int j = i + 2;
        if (j < NKI) k2_load_stage(sb, tid, j, Zb, Wb);
        CP_COMMIT();
    }

    int g = lane >> 2, t4 = lane & 3;
    #pragma unroll
    for (int mt = 0; mt < 2; mt++) {
        #pragma unroll
        for (int nt = 0; nt < 8; nt++) {
            int r0 = row0 + wm*32 + mt*16 + g;
            int c  = n0 + wn*64 + nt*8 + 2*t4;
            float b0v = __ldg(bc + c), b1v = __ldg(bc + c + 1);
            __nv_bfloat162 o0, o1;
            o0.x = __float2bfloat16(gelu(acc[mt][nt][0] + b0v));
            o0.y = __float2bfloat16(gelu(acc[mt][nt][1] + b1v));
            o1.x = __float2bfloat16(gelu(acc[mt][nt][2] + b0v));
            o1.y = __float2bfloat16(gelu(acc[mt][nt][3] + b1v));
            *(uint32_t*)(g_Yb + (size_t)r0 * H + c) = *(uint32_t*)&o0;
            *(uint32_t*)(g_Yb + (size_t)(r0 + 8) * H + c) = *(uint32_t*)&o1;
        }
    }
}

// ---------------------------------------------------------------------------
// k3: logits = Yb @ W3^T + b_crf -> ner_scores (+ pads), via bf16 mma.
// ---------------------------------------------------------------------------
#define STG3 (128*128 + 64*128)   // 24576 bytes
#define SMEM_K3 (3*STG3)          // 73728
#define NKI3 (H/64)               // 16

__device__ __forceinline__ void k3_load_stage(
    uint32_t sb, int tid, int j, const char* Yb)
{
    uint32_t base = sb + (j % 3) * STG3;
    int kb = j * 128;
    #pragma unroll
    for (int q = 0; q < 6; q++) {
        int idx = tid + 256*q;
        if (q < 4) {
            int m = idx >> 3, c = idx & 7;
            cp16(base + ((m*128 + c*16) ^ ((m & 7) << 4)),
                 Yb + (size_t)m * (H*2) + kb + c*16);
        } else {
            int ci = idx - 1024;
            int n = ci >> 3, c = ci & 7;
            cp16(base + 16384 + ((n*128 + c*16) ^ ((n & 7) << 4)),
                 (const char*)g_W3 + (size_t)n * (H*2) + kb + c*16);
        }
    }
}

__global__ __launch_bounds__(256, 2) void k3_mma(
    const float* __restrict__ bcrf, float* __restrict__ out)
{
    extern __shared__ __align__(16) char smem[];
    uint32_t sb = smem_u32(smem);
    int tid = threadIdx.x, lane = tid & 31, wid = tid >> 5;
    int wm = wid & 3, wn = wid >> 2;          // 4 x 2
    int row0 = blockIdx.x * 128;

    const char* Yb = (const char*)g_Yb + (size_t)row0 * (H*2);

    float acc[2][4][4];
    #pragma unroll
    for (int mt = 0; mt < 2; mt++)
        #pragma unroll
        for (int nt = 0; nt < 4; nt++)
            #pragma unroll
            for (int q = 0; q < 4; q++) acc[mt][nt][q] = 0.f;

    k3_load_stage(sb, tid, 0, Yb); CP_COMMIT();
    k3_load_stage(sb, tid, 1, Yb); CP_COMMIT();

    int r15 = lane & 15;
    int hb  = (lane >> 4) << 4;

    for (int i = 0; i < NKI3; i++) {
        CP_WAIT(1);
        __syncthreads();

        uint32_t Ab = sb + (i % 3) * STG3;
        uint32_t Bb = Ab + 16384;
        #pragma unroll
        for (int kk = 0; kk < 4; kk++) {
            int kbyte = kk*32 + hb;
            uint32_t a[2][4];
            #pragma unroll
            for (int mt = 0; mt < 2; mt++) {
                int rr = wm*32 + mt*16 + r15;
                ldsm4(a[mt], Ab + rr*128 + (kbyte ^ ((rr & 7) << 4)));
            }
            #pragma unroll
            for (int np = 0; np < 2; np++) {
                int nr = wn*32 + np*16 + r15;
                uint32_t b[4];
                ldsm4(b, Bb + nr*128 + (kbyte ^ ((nr & 7) << 4)));
                #pragma unroll
                for (int mt = 0; mt < 2; mt++) {
                    mma_bf16(acc[mt][2*np],   a[mt], b[0], b[2]);
                    mma_bf16(acc[mt][2*np+1], a[mt], b[1], b[3]);
                }
            }
        }

        int j = i + 2;
        if (j < NKI3) k3_load_stage(sb, tid, j, Yb);
        CP_COMMIT();
    }

    int g = lane >> 2, t4 = lane & 3;
    #pragma unroll
    for (int mt = 0; mt < 2; mt++) {
        int r = row0 + wm*32 + mt*16 + g;
        #pragma unroll
        for (int nt = 0; nt < 4; nt++) {
            int c0 = wn*32 + nt*8 + 2*t4, c1 = c0 + 1;
            if (c0 < T) {
                float bv = __ldg(bcrf + c0);
                out[(size_t)r*LP + c0]     = acc[mt][nt][0] + bv;
                out[(size_t)(r+8)*LP + c0] = acc[mt][nt][2] + bv;
            }
            if (c1 < T) {
                float bv = __ldg(bcrf + c1);
                out[(size_t)r*LP + c1]     = acc[mt][nt][1] + bv;
                out[(size_t)(r+8)*LP + c1] = acc[mt][nt][3] + bv;
            }
        }
        if (wn == 1 && t4 == 0) {
            out[(size_t)r*LP + 37] = -10000.f;  out[(size_t)r*LP + 38] = -10000.f;
            out[(size_t)(r+8)*LP + 37] = -10000.f; out[(size_t)(r+8)*LP + 38] = -10000.f;
        }
    }
}

// ---------------------------------------------------------------------------
// k4: CRF loglik. One warp per batch; lagged-shift LSE scan (exact).
// ---------------------------------------------------------------------------
__global__ __launch_bounds__(32) void k4_crf(
    const float* __restrict__ scores, const int* __restrict__ labels,
    const int* __restrict__ lens, const float* __restrict__ trans,
    float* __restrict__ loss)
{
    extern __shared__ float sc[];
    int b = blockIdx.x;
    int lane = threadIdx.x;
    int len = lens[b];
    const int* lab = labels + b*S;

    {
        uint32_t sbase = smem_u32(sc);
        const float4* src = (const float4*)(scores + (size_t)b * S * LP);
        for (int i = lane; i < S*LP/4; i += 32)
            cp16(sbase + i*16, src + i);
        CP_COMMIT();
        CP_WAIT(0);
        __syncwarp();
    }

    float ET0[LP], ET1[LP], maxT0 = -1e30f, maxT1 = -1e30f;
    {
        const float* tr = trans + lane*LP;
        #pragma unroll
        for (int f = 0; f < LP; f++) maxT0 = fmaxf(maxT0, tr[f]);
        #pragma unroll
        for (int f = 0; f < LP; f++) ET0[f] = __expf(tr[f] - maxT0);
    }
    if (lane < LP-32) {
        const float* tr = trans + (32+lane)*LP;
        #pragma unroll
        for (int f = 0; f < LP; f++) maxT1 = fmaxf(maxT1, tr[f]);
        #pragma unroll
        for (int f = 0; f < LP; f++) ET1[f] = __expf(tr[f] - maxT1);
    }

    float g = 0.f;
    for (int s2 = lane; s2 < len; s2 += 32) g += sc[s2*LP + lab[s2]];
    for (int i = lane; i <= len; i += 32) {
        int frm = (i == 0)   ? T       : lab[i-1];
        int to  = (i == len) ? (T + 1) : lab[i];
        g += trans[to*LP + frm];
    }
    #pragma unroll
    for (int o = 16; o; o >>= 1) g += __shfl_xor_sync(~0u, g, o);

    float a0 = -100.f;
    float a1 = (lane == (T - 32)) ? 0.f : -100.f;
    float s_cur = 0.f, s_next = 0.f;

    for (int t = 0; t < len; t++) {
        float e0 = __expf(a0 - s_cur);
        float e1 = (lane < LP-32) ? __expf(a1 - s_cur) : 0.f;
        float s0a = 0.f, s0b = 0.f, s1a = 0.f, s1b = 0.f;
        #pragma unroll
        for (int f = 0; f < 32; f += 2) {
            float ea = __shfl_sync(~0u, e0, f);
            float eb = __shfl_sync(~0u, e0, f+1);
            s0a += ea*ET0[f];   s0b += eb*ET0[f+1];
            s1a += ea*ET1[f];   s1b += eb*ET1[f+1];
        }
        #pragma unroll
        for (int f = 0; f < LP-32; f++) {
            float ea = __shfl_sync(~0u, e1, f);
            s0a += ea*ET0[32+f];
            s1a += ea*ET1[32+f];
        }
        a0 = sc[t*LP + lane] + s_cur + maxT0 + __logf(s0a + s0b);
        if (lane < LP-32)
            a1 = sc[t*LP + 32 + lane] + s_cur + maxT1 + __logf(s1a + s1b);
        float m = rmax32(fmaxf(a0, (lane < LP-32) ? a1 : -1e30f));
        s_cur = s_next;
        s_next = m;
    }

    a0 += trans[(T+1)*LP + lane];
    if (lane < LP-32) a1 += trans[(T+1)*LP + 32 + lane];
    float v = rmax32(fmaxf(a0, (lane < LP-32) ? a1 : -1e30f));
    float e = __expf(a0 - v) + ((lane < LP-32) ? __expf(a1 - v) : 0.f);
    #pragma unroll
    for (int o = 16; o; o >>= 1) e += __shfl_xor_sync(~0u, e, o);
    if (lane == 0) loss[b] = g - (v + logf(e));
}

// ---------------------------------------------------------------------------
extern "C" void kernel_launch(void* const* d_in, const int* in_sizes, int n_in,
                              void* d_out, int out_size)
{
    const float* h      = (const float*)d_in[0];
    const int*   lens   = (const int*)d_in[2];
    const int*   labels = (const int*)d_in[3];
    const float* bio    = (const float*)d_in[4];
    const float* W_cat  = (const float*)d_in[5];
    const float* b_cat  = (const float*)d_in[6];
    const float* W_crf  = (const float*)d_in[7];
    const float* b_crf  = (const float*)d_in[8];
    const float* trans  = (const float*)d_in[9];

    float* out = (float*)d_out;            // ner_scores [B,S,LP] then loss [B]
    float* loss = out + (size_t)B * S * LP;

    size_t smemF  = (size_t)(T*H) * sizeof(__nv_bfloat16);  // 75776 (max of branches)
    size_t smem4  = (size_t)(S*LP) * sizeof(float);         // 79872

    static int attr_done = 0;
    if (!attr_done) {
        cudaFuncSetAttribute(kfused, cudaFuncAttributeMaxDynamicSharedMemorySize, (int)smemF);
        cudaFuncSetAttribute(k2_mma, cudaFuncAttributeMaxDynamicSharedMemorySize, SMEM_K2);
        cudaFuncSetAttribute(k3_mma, cudaFuncAttributeMaxDynamicSharedMemorySize, SMEM_K3);
        cudaFuncSetAttribute(k4_crf, cudaFuncAttributeMaxDynamicSharedMemorySize, (int)smem4);
        attr_done = 1;
    }

    kfused<<<3392, 256, smemF>>>(h, bio, W_cat, W_crf);
    kfin<<<H*64/256, 256>>>();
    k2_mma<<<dim3(H/KBN, BS/KBM), 256, SMEM_K2>>>(b_cat);
    k3_mma<<<BS/128, 256, SMEM_K3>>>(b_crf, out);
    k4_crf<<<B, 32, smem4>>>(out, labels, lens, trans, loss);
}